// round 4
// baseline (speedup 1.0000x reference)
#include <cuda_runtime.h>
#include <math.h>
#include <stdint.h>

#define BB 256
#define TT 32
#define SS 128
#define II 256
#define HH 1024
#define OO 256
#define G4 4096

// ---------------- scratch (static device globals; no allocation) ------------
__device__ float d_Xg[(size_t)TT * BB * G4];   // [T][B][4H] input gates + biases
__device__ float d_h[2][BB * HH];              // double-buffered hidden state (fp32)
__device__ uint32_t d_ht32[2][BB * HH];        // double-buffered hidden, tf32 fragment-permuted
__device__ float d_c[BB * HH];
__device__ float d_u[2][BB * 2 * HH];          // double-buffered [ctx|h] for FC
__device__ float d_fcp[2][4][BB * OO];         // split-K FC partials
__device__ uint32_t d_Wih_t[G4 * II];          // tf32 (plain layout)
__device__ uint32_t d_Whh_t[(size_t)G4 * HH];  // tf32, fragment-permuted within k8 groups
__device__ uint32_t d_Wfc_t[OO * 2 * HH];      // tf32 (plain layout)

// ---------------- helpers ----------------------------------------------------
__device__ __forceinline__ uint32_t f2tf32(float x) {
    uint32_t r;
    asm("cvt.rna.tf32.f32 %0, %1;" : "=r"(r) : "f"(x));
    return r;
}
__device__ __forceinline__ uint32_t cvta_s(const void* p) {
    return (uint32_t)__cvta_generic_to_shared(p);
}
// permute k within its 8-group so (k, k+4) become adjacent: j = 2*(k&3) + ((k>>2)&1)
__device__ __forceinline__ int kperm(int k) {
    return (k & ~7) + ((k & 3) << 1) + ((k >> 2) & 1);
}
#define CPASYNC16(sa, g) asm volatile("cp.async.cg.shared.global [%0], [%1], 16;" :: "r"(sa), "l"(g))
#define CPASYNC16Z(sa, g, sz) asm volatile("cp.async.cg.shared.global [%0], [%1], 16, %2;" :: "r"(sa), "l"(g), "r"(sz))
#define CPCOMMIT() asm volatile("cp.async.commit_group;")
#define CPWAIT(n) asm volatile("cp.async.wait_group %0;" :: "n"(n))

__device__ __forceinline__ void mma_tf32(float c[4], const uint32_t a[4], const uint32_t b[2]) {
    asm volatile(
        "mma.sync.aligned.m16n8k8.row.col.f32.tf32.tf32.f32 "
        "{%0,%1,%2,%3}, {%4,%5,%6,%7}, {%8,%9}, {%0,%1,%2,%3};"
        : "+f"(c[0]), "+f"(c[1]), "+f"(c[2]), "+f"(c[3])
        : "r"(a[0]), "r"(a[1]), "r"(a[2]), "r"(a[3]), "r"(b[0]), "r"(b[1]));
}

#define SIG(x) (1.f / (1.f + __expf(-(x))))

// ========== precompute GEMM (k_pre only): 128x128 tiles, depth-2 =============
__device__ __forceinline__ void gemm_pre(
    int ctam, int ctan,
    const float* __restrict__ Ag, const uint32_t* __restrict__ Bt,
    const float* __restrict__ e1, const float* __restrict__ e2,
    float* __restrict__ Cout, int K, char* dyn)
{
    float* As = (float*)dyn;
    uint32_t* Bs = (uint32_t*)(dyn + 36864);
    const int tid = threadIdx.x;
    const int lane = tid & 31;
    const int wid = tid >> 5;
    const int wm = wid & 3;
    const int wn = wid >> 2;
    const int tg = lane & 3;
    const int gp = lane >> 2;

    float acc[2][8][4];
#pragma unroll
    for (int i = 0; i < 2; ++i)
#pragma unroll
        for (int j = 0; j < 8; ++j)
#pragma unroll
            for (int k = 0; k < 4; ++k) acc[i][j][k] = 0.f;

    const int nc = K >> 5;
    auto stage = [&](int buf, int kc) {
#pragma unroll
        for (int it = 0; it < 4; ++it) {
            int slot = it * 256 + tid;
            int row = slot >> 3;
            int cc = (slot & 7) << 2;
            uint32_t sa = cvta_s(As + buf * 4608 + row * 36 + cc);
            int m = ctam * 128 + row;
            int t_ = m >> 8;
            int b_ = m & 255;
            const float* ga = (t_ == 0) ? Ag : Ag + ((size_t)b_ * TT + t_) * II + kc + cc;
            int sz = (t_ == 0) ? 0 : 16;
            CPASYNC16Z(sa, ga, sz);
            uint32_t sb = cvta_s(Bs + buf * 4608 + row * 36 + cc);
            CPASYNC16(sb, Bt + (size_t)(ctan * 128 + row) * K + kc + cc);
        }
    };

    stage(0, 0);
    CPCOMMIT();
    for (int c = 0; c < nc; ++c) {
        if (c + 1 < nc) stage((c + 1) & 1, (c + 1) * 32);
        CPCOMMIT();
        CPWAIT(1);
        __syncthreads();
        const float* Af = As + (c & 1) * 4608;
        const uint32_t* Bf = Bs + (c & 1) * 4608;
#pragma unroll
        for (int ks = 0; ks < 4; ++ks) {
            uint32_t a[2][4], b[8][2];
#pragma unroll
            for (int mt = 0; mt < 2; ++mt) {
                int r = wm * 32 + mt * 16 + gp;
                a[mt][0] = f2tf32(Af[r * 36 + ks * 8 + tg]);
                a[mt][1] = f2tf32(Af[(r + 8) * 36 + ks * 8 + tg]);
                a[mt][2] = f2tf32(Af[r * 36 + ks * 8 + tg + 4]);
                a[mt][3] = f2tf32(Af[(r + 8) * 36 + ks * 8 + tg + 4]);
            }
#pragma unroll
            for (int nt = 0; nt < 8; ++nt) {
                int n = wn * 64 + nt * 8 + gp;
                b[nt][0] = Bf[n * 36 + ks * 8 + tg];
                b[nt][1] = Bf[n * 36 + ks * 8 + tg + 4];
            }
#pragma unroll
            for (int mt = 0; mt < 2; ++mt)
#pragma unroll
                for (int nt = 0; nt < 8; ++nt)
                    mma_tf32(acc[mt][nt], a[mt], b[nt]);
        }
        __syncthreads();
    }
#pragma unroll
    for (int mt = 0; mt < 2; ++mt)
#pragma unroll
        for (int nt = 0; nt < 8; ++nt) {
            int gm0 = ctam * 128 + wm * 32 + mt * 16 + gp;
            int gn = ctan * 128 + wn * 64 + nt * 8 + tg * 2;
#pragma unroll
            for (int half = 0; half < 2; ++half) {
                int gm = gm0 + half * 8;
                float v0 = acc[mt][nt][half * 2 + 0] + e1[gn] + e2[gn];
                float v1 = acc[mt][nt][half * 2 + 1] + e1[gn + 1] + e2[gn + 1];
                *(float2*)(Cout + (size_t)gm * G4 + gn) = make_float2(v0, v1);
            }
        }
}

// ========== fused gates GEMM + LSTM cell (fragment-permuted tf32) =============
// Tile: 64 M x (4 gates x 32 hidden cols). grid 4 x 32 = 128 CTAs.
// K-chunk 64, depth-3. smem: As u32 [3][64][72] @0 (55296 B),
//                            Bs u32 [3][128][72] @55296 (110592 B)
// epilogue reuse: ep fp32 [64][132] @0 (33792 B, fits in As region)
__device__ __forceinline__ void gatescell_dev(
    int ctam, int ctan,
    const uint32_t* __restrict__ hA,   // h_{t-1}, tf32 permuted
    const float* __restrict__ Xg,      // d_Xg + t*BB*G4
    float* __restrict__ hOut,          // h_t fp32
    uint32_t* __restrict__ hOut32,     // h_t tf32 permuted
    char* dyn)
{
    uint32_t* As = (uint32_t*)dyn;
    uint32_t* Bs = (uint32_t*)(dyn + 55296);
    const int tid = threadIdx.x;
    const int lane = tid & 31;
    const int wid = tid >> 5;
    const int wm = wid & 1;      // 2 M halves of 32 rows
    const int g = wid >> 1;      // warp owns one gate (0..3)
    const int tg = lane & 3;
    const int gp = lane >> 2;
    const int q0 = ctan * 32;
    const int m0 = ctam * 64;

    float acc[2][4][4];
#pragma unroll
    for (int i = 0; i < 2; ++i)
#pragma unroll
        for (int j = 0; j < 4; ++j)
#pragma unroll
            for (int k = 0; k < 4; ++k) acc[i][j][k] = 0.f;

    auto stage = [&](int buf, int kc) {
        // A: 64x64 u32 = 1024 x 16B, 4 per thread
#pragma unroll
        for (int it = 0; it < 4; ++it) {
            int slot = it * 256 + tid;
            int row = slot >> 4;
            int cc = (slot & 15) << 2;
            CPASYNC16(cvta_s(As + buf * 4608 + row * 72 + cc),
                      hA + (size_t)(m0 + row) * HH + kc + cc);
        }
        // B: 128x64 u32 = 2048 x 16B, 8 per thread; rows gather 4 gate blocks
#pragma unroll
        for (int it = 0; it < 8; ++it) {
            int slot = it * 256 + tid;
            int row = slot >> 4;
            int cc = (slot & 15) << 2;
            int wr = (row >> 5) * HH + q0 + (row & 31);
            CPASYNC16(cvta_s(Bs + buf * 9216 + row * 72 + cc),
                      d_Whh_t + (size_t)wr * HH + kc + cc);
        }
    };

    stage(0, 0); CPCOMMIT();
    stage(1, 64); CPCOMMIT();
    const int nc = 16;  // K=1024 / 64
    for (int c = 0; c < nc; ++c) {
        if (c + 2 < nc) stage((c + 2) % 3, (c + 2) * 64);
        CPCOMMIT();
        CPWAIT(2);
        __syncthreads();
        const uint32_t* Af = As + (c % 3) * 4608;
        const uint32_t* Bf = Bs + (c % 3) * 9216;
#pragma unroll
        for (int ks = 0; ks < 8; ++ks) {
            uint32_t a[2][4], b[4][2];
#pragma unroll
            for (int mt = 0; mt < 2; ++mt) {
                int r = wm * 32 + mt * 16 + gp;
                uint2 lo = *(const uint2*)(Af + r * 72 + ks * 8 + tg * 2);
                uint2 hi = *(const uint2*)(Af + (r + 8) * 72 + ks * 8 + tg * 2);
                a[mt][0] = lo.x; a[mt][2] = lo.y;
                a[mt][1] = hi.x; a[mt][3] = hi.y;
            }
#pragma unroll
            for (int nt = 0; nt < 4; ++nt) {
                int n = g * 32 + nt * 8 + gp;
                uint2 v = *(const uint2*)(Bf + n * 72 + ks * 8 + tg * 2);
                b[nt][0] = v.x; b[nt][1] = v.y;
            }
#pragma unroll
            for (int mt = 0; mt < 2; ++mt)
#pragma unroll
                for (int nt = 0; nt < 4; ++nt)
                    mma_tf32(acc[mt][nt], a[mt], b[nt]);
        }
        __syncthreads();
    }

    // gate exchange: ep[row 64][n 128], n = g*32 + qq, stride 132
    float* ep = (float*)dyn;
    __syncthreads();
#pragma unroll
    for (int mt = 0; mt < 2; ++mt)
#pragma unroll
        for (int nt = 0; nt < 4; ++nt) {
            int r0 = wm * 32 + mt * 16 + gp;
            int col = g * 32 + nt * 8 + tg * 2;
            *(float2*)(ep + r0 * 132 + col) = make_float2(acc[mt][nt][0], acc[mt][nt][1]);
            *(float2*)(ep + (r0 + 8) * 132 + col) = make_float2(acc[mt][nt][2], acc[mt][nt][3]);
        }
    __syncthreads();

    // cell: 2048 elems, 8 per thread
#pragma unroll
    for (int k = 0; k < 8; ++k) {
        int idx = k * 256 + tid;
        int row = idx >> 5;
        int qq = idx & 31;
        int b = m0 + row;
        int q = q0 + qq;
        size_t xb = (size_t)b * G4 + q;
        float vi = ep[row * 132 + qq]        + Xg[xb];
        float vf = ep[row * 132 + 32 + qq]   + Xg[xb + HH];
        float vg = ep[row * 132 + 64 + qq]   + Xg[xb + 2 * HH];
        float vo = ep[row * 132 + 96 + qq]   + Xg[xb + 3 * HH];
        size_t hb = (size_t)b * HH + q;
        float c_old = d_c[hb];
        float c_new = SIG(vf) * c_old + SIG(vi) * tanhf(vg);
        float h_new = SIG(vo) * tanhf(c_new);
        d_c[hb] = c_new;
        hOut[hb] = h_new;
        hOut32[(size_t)b * HH + kperm(q)] = f2tf32(h_new);
    }
}

// ========== FC split-K partial GEMM ==========================================
// Tile 128M x 64N, K-slice 512 (16 chunks), depth-3. grid 2x4x4 = 32 CTAs.
// smem: Af fp32 [3][128][36] @0 (55296), Bf u32 [3][64][36] @55296 (27648)
__device__ __forceinline__ void fcpart_dev(
    int ctam, int ctan, int kslice,
    const float* __restrict__ u,       // [256][2048]
    float* __restrict__ part)          // [256][256]
{
    extern __shared__ char dyn[];
    float* Af = (float*)dyn;
    uint32_t* Bf = (uint32_t*)(dyn + 55296);
    const int tid = threadIdx.x;
    const int lane = tid & 31;
    const int wid = tid >> 5;
    const int wm = wid & 3;
    const int wn = wid >> 2;
    const int tg = lane & 3;
    const int gp = lane >> 2;
    const int k0 = kslice * 512;

    float acc[2][4][4];
#pragma unroll
    for (int i = 0; i < 2; ++i)
#pragma unroll
        for (int j = 0; j < 4; ++j)
#pragma unroll
            for (int k = 0; k < 4; ++k) acc[i][j][k] = 0.f;

    auto stage = [&](int buf, int kc) {
#pragma unroll
        for (int it = 0; it < 4; ++it) {
            int slot = it * 256 + tid;
            int row = slot >> 3;
            int cc = (slot & 7) << 2;
            CPASYNC16(cvta_s(Af + buf * 4608 + row * 36 + cc),
                      u + (size_t)(ctam * 128 + row) * (2 * HH) + k0 + kc + cc);
        }
#pragma unroll
        for (int it = 0; it < 2; ++it) {
            int slot = it * 256 + tid;
            int row = slot >> 3;
            int cc = (slot & 7) << 2;
            CPASYNC16(cvta_s(Bf + buf * 2304 + row * 36 + cc),
                      d_Wfc_t + (size_t)(ctan * 64 + row) * (2 * HH) + k0 + kc + cc);
        }
    };

    stage(0, 0); CPCOMMIT();
    stage(1, 32); CPCOMMIT();
    const int nc = 16;
    for (int c = 0; c < nc; ++c) {
        if (c + 2 < nc) stage((c + 2) % 3, (c + 2) * 32);
        CPCOMMIT();
        CPWAIT(2);
        __syncthreads();
        const float* A = Af + (c % 3) * 4608;
        const uint32_t* B = Bf + (c % 3) * 2304;
#pragma unroll
        for (int kk = 0; kk < 4; ++kk) {
            uint32_t a[2][4], b[4][2];
#pragma unroll
            for (int mt = 0; mt < 2; ++mt) {
                int r = wm * 32 + mt * 16 + gp;
                a[mt][0] = f2tf32(A[r * 36 + kk * 8 + tg]);
                a[mt][1] = f2tf32(A[(r + 8) * 36 + kk * 8 + tg]);
                a[mt][2] = f2tf32(A[r * 36 + kk * 8 + tg + 4]);
                a[mt][3] = f2tf32(A[(r + 8) * 36 + kk * 8 + tg + 4]);
            }
#pragma unroll
            for (int nt = 0; nt < 4; ++nt) {
                int n = wn * 32 + nt * 8 + gp;
                b[nt][0] = B[n * 36 + kk * 8 + tg];
                b[nt][1] = B[n * 36 + kk * 8 + tg + 4];
            }
#pragma unroll
            for (int mt = 0; mt < 2; ++mt)
#pragma unroll
                for (int nt = 0; nt < 4; ++nt)
                    mma_tf32(acc[mt][nt], a[mt], b[nt]);
        }
        __syncthreads();
    }
#pragma unroll
    for (int mt = 0; mt < 2; ++mt)
#pragma unroll
        for (int nt = 0; nt < 4; ++nt) {
            int gm0 = ctam * 128 + wm * 32 + mt * 16 + gp;
            int gn = ctan * 64 + wn * 32 + nt * 8 + tg * 2;
            *(float2*)(part + (size_t)gm0 * OO + gn) =
                make_float2(acc[mt][nt][0], acc[mt][nt][1]);
            *(float2*)(part + (size_t)(gm0 + 8) * OO + gn) =
                make_float2(acc[mt][nt][2], acc[mt][nt][3]);
        }
}

// ========== attention (cp.async pipelined single-pass softmax) ================
__device__ __forceinline__ void attn_dev(int b, int tatt, const float* __restrict__ enc,
                                         const float* __restrict__ hcur,
                                         float* __restrict__ out, int par, char* dyn,
                                         float* s_scores, float* s_m, float* s_l)
{
    float* es = (float*)dyn;
    const int tid = threadIdx.x;
    const int lane = tid & 31;
    const int w = tid >> 5;

    const float* hb = hcur + (size_t)b * HH;
    float hreg[32];
#pragma unroll
    for (int i = 0; i < 32; ++i) hreg[i] = hb[i * 32 + lane];

    const float* encb = enc + (size_t)b * SS * HH;
#pragma unroll
    for (int p = 0; p < 3; ++p) {
        const float* gsrc = encb + (size_t)(w * 16 + p) * HH;
        float* sb = es + ((size_t)(p % 3) * 8 + w) * 1024;
#pragma unroll
        for (int q = 0; q < 8; ++q)
            CPASYNC16(cvta_s(sb + q * 128 + lane * 4), gsrc + q * 128 + lane * 4);
        CPCOMMIT();
    }

    float m = -1e30f, l = 0.f;
    float ctx[32];
#pragma unroll
    for (int i = 0; i < 32; ++i) ctx[i] = 0.f;

    for (int j = 0; j < 16; ++j) {
        CPWAIT(2);
        __syncwarp();
        const float* e = es + ((size_t)(j % 3) * 8 + w) * 1024;
        float dot = 0.f;
#pragma unroll
        for (int i = 0; i < 32; ++i) dot += hreg[i] * e[i * 32 + lane];
#pragma unroll
        for (int o = 16; o; o >>= 1) dot += __shfl_xor_sync(0xffffffffu, dot, o);
        if (lane == 0) s_scores[w * 16 + j] = dot;

        float nm = fmaxf(m, dot);
        float al = __expf(m - nm);
        float p = __expf(dot - nm);
        l = l * al + p;
#pragma unroll
        for (int i = 0; i < 32; ++i) ctx[i] = ctx[i] * al + p * e[i * 32 + lane];
        m = nm;
        __syncwarp();
        if (j + 3 < 16) {
            const float* gsrc = encb + (size_t)(w * 16 + j + 3) * HH;
            float* sb = es + ((size_t)(j % 3) * 8 + w) * 1024;
#pragma unroll
            for (int q = 0; q < 8; ++q)
                CPASYNC16(cvta_s(sb + q * 128 + lane * 4), gsrc + q * 128 + lane * 4);
        }
        CPCOMMIT();
    }
    CPWAIT(0);
    if (lane == 0) { s_m[w] = m; s_l[w] = l; }
    __syncthreads();

    float M = -1e30f;
#pragma unroll
    for (int i = 0; i < 8; ++i) M = fmaxf(M, s_m[i]);
    float L = 0.f;
#pragma unroll
    for (int i = 0; i < 8; ++i) L += s_l[i] * __expf(s_m[i] - M);

    float sc = __expf(m - M);
    float* cs = es + (size_t)w * 1024;
#pragma unroll
    for (int i = 0; i < 32; ++i) cs[i * 32 + lane] = ctx[i] * sc;
    __syncthreads();

    float* ubuf = d_u[par];
    for (int kk = tid; kk < HH; kk += 256) {
        float sum = 0.f;
#pragma unroll
        for (int ww = 0; ww < 8; ++ww) sum += es[(size_t)ww * 1024 + kk];
        ubuf[(size_t)b * 2 * HH + kk] = sum / L;
        ubuf[(size_t)b * 2 * HH + HH + kk] = hb[kk];
    }
    if (tid < SS) {
        float p = __expf(s_scores[tid] - M) / L;
        out[(size_t)BB * TT * OO + (size_t)b * TT * SS + (size_t)tatt * SS + tid] = p;
    }
}

// ---------------- kernels -----------------------------------------------------
__global__ void k_init() {
    int g = blockIdx.x * 256 + threadIdx.x;  // 65536 float4s per array
    float4 z = make_float4(0.f, 0.f, 0.f, 0.f);
    ((float4*)d_h[1])[g] = z;
    ((float4*)d_ht32[1])[g] = z;
    ((float4*)d_c)[g] = z;
}

__global__ void __launch_bounds__(256) k_convert(const float* __restrict__ Wih,
                                                 const float* __restrict__ Whh,
                                                 const float* __restrict__ Wfc) {
    int g = blockIdx.x * 256 + threadIdx.x;
    int stride = gridDim.x * 256;
    for (int i = g; i < G4 * II; i += stride) d_Wih_t[i] = f2tf32(Wih[i]);
    for (int i = g; i < G4 * HH; i += stride) {
        int n = i >> 10;
        int k = i & 1023;
        d_Whh_t[(size_t)n * HH + kperm(k)] = f2tf32(Whh[i]);
    }
    for (int i = g; i < OO * 2 * HH; i += stride) d_Wfc_t[i] = f2tf32(Wfc[i]);
}

__global__ void __launch_bounds__(256, 2) k_pre(const float* __restrict__ st,
                                                const float* __restrict__ bih,
                                                const float* __restrict__ bhh) {
    extern __shared__ char dyn[];
    gemm_pre(blockIdx.x >> 5, blockIdx.x & 31, st, d_Wih_t, bih, bhh, d_Xg, II, dyn);
}

__global__ void __launch_bounds__(256) kA(int t, int nG, int nA, int nP,
                                          const float* __restrict__ enc,
                                          const float* __restrict__ bfc,
                                          float* __restrict__ out) {
    extern __shared__ char dyn[];
    __shared__ float s_scores[SS];
    __shared__ float s_m[8], s_l[8];
    int bid = blockIdx.x;
    if (bid < nG) {
        gatescell_dev(bid >> 5, bid & 31,
                      d_ht32[(t + 1) & 1], d_Xg + (size_t)t * BB * G4,
                      d_h[t & 1], d_ht32[t & 1], dyn);
    } else if (bid < nG + nA) {
        int ta = t - 1;
        attn_dev(bid - nG, ta, enc, d_h[ta & 1], out, ta & 1, dyn, s_scores, s_m, s_l);
    } else if (bid < nG + nA + nP) {
        int f = bid - nG - nA;     // 0..31
        int tfc = t - 2;
        int ks = f & 3;
        int ctan = (f >> 2) & 3;
        int ctam = f >> 4;
        fcpart_dev(ctam, ctan, ks, d_u[tfc & 1], d_fcp[tfc & 1][ks]);
    } else {
        int tr = t - 3;
        const float* p0 = d_fcp[tr & 1][0];
        const float* p1 = d_fcp[tr & 1][1];
        const float* p2 = d_fcp[tr & 1][2];
        const float* p3 = d_fcp[tr & 1][3];
        int bidr = bid - nG - nA - nP;  // 0..15
        for (int e = bidr * 256 + threadIdx.x; e < BB * OO; e += 16 * 256) {
            int b = e >> 8;
            int o = e & 255;
            float v = p0[e] + p1[e] + p2[e] + p3[e] + bfc[o];
            out[(size_t)b * TT * OO + (size_t)tr * OO + o] = v;
        }
    }
}

// ---------------- launch --------------------------------------------------------
extern "C" void kernel_launch(void* const* d_in, const int* in_sizes, int n_in,
                              void* d_out, int out_size) {
    const float* st  = (const float*)d_in[0];
    const float* enc = (const float*)d_in[1];
    const float* Wih = (const float*)d_in[2];
    const float* Whh = (const float*)d_in[3];
    const float* bih = (const float*)d_in[4];
    const float* bhh = (const float*)d_in[5];
    const float* Wfc = (const float*)d_in[6];
    const float* bfc = (const float*)d_in[7];
    float* out = (float*)d_out;

    static const int DYN_GEMM = 73728;
    static const int DYN_KA = 165888;   // gates: 55296(A) + 110592(B)
    cudaFuncSetAttribute(k_pre, cudaFuncAttributeMaxDynamicSharedMemorySize, DYN_GEMM);
    cudaFuncSetAttribute(kA, cudaFuncAttributeMaxDynamicSharedMemorySize, DYN_KA);

    k_init<<<256, 256>>>();                       // 0
    k_convert<<<592, 256>>>(Wih, Whh, Wfc);       // 1
    k_pre<<<2048, 256, DYN_GEMM>>>(st, bih, bhh); // 2

    // 3: kA(0), 4: kA(1), 5: kA(2) <- ncu -s 5 profiles mixed gates+attn+fc
    for (int t = 0; t <= TT + 2; ++t) {
        int nG = (t < TT) ? 128 : 0;                     // gates+cell step t
        int nA = (t >= 1 && t <= TT) ? BB : 0;           // attention step t-1
        int nP = (t >= 2 && t <= TT + 1) ? 32 : 0;       // fc partials step t-2
        int nR = (t >= 3) ? 16 : 0;                      // fc reduce step t-3
        kA<<<nG + nA + nP + nR, 256, DYN_KA>>>(t, nG, nA, nP, enc, bfc, out);
    }
}

// round 5
// speedup vs baseline: 1.2514x; 1.2514x over previous
#include <cuda_runtime.h>
#include <math.h>
#include <stdint.h>

#define BB 256
#define TT 32
#define SS 128
#define II 256
#define HH 1024
#define OO 256
#define G4 4096

// ---------------- scratch (static device globals; no allocation) ------------
__device__ float d_Xg[(size_t)TT * BB * G4];   // [T][B][4H] input gates + biases
__device__ float d_h[2][BB * HH];              // double-buffered hidden state (fp32)
__device__ uint32_t d_ht32[2][BB * HH];        // double-buffered hidden, tf32 fragment-permuted
__device__ float d_c[BB * HH];
__device__ float d_u[2][BB * 2 * HH];          // double-buffered [ctx|h] for FC
__device__ float d_fcp[2][4][BB * OO];         // split-K FC partials
__device__ uint32_t d_Wih_t[G4 * II];          // tf32 (plain layout)
__device__ uint32_t d_Whh_t[(size_t)G4 * HH];  // tf32, fragment-permuted within k8 groups
__device__ uint32_t d_Wfc_t[OO * 2 * HH];      // tf32 (plain layout)

// ---------------- helpers ----------------------------------------------------
__device__ __forceinline__ uint32_t f2tf32(float x) {
    uint32_t r;
    asm("cvt.rna.tf32.f32 %0, %1;" : "=r"(r) : "f"(x));
    return r;
}
__device__ __forceinline__ uint32_t cvta_s(const void* p) {
    return (uint32_t)__cvta_generic_to_shared(p);
}
// permute k within its 8-group so (k, k+4) become adjacent: j = 2*(k&3) + ((k>>2)&1)
__device__ __forceinline__ int kperm(int k) {
    return (k & ~7) + ((k & 3) << 1) + ((k >> 2) & 1);
}
#define CPASYNC16(sa, g) asm volatile("cp.async.cg.shared.global [%0], [%1], 16;" :: "r"(sa), "l"(g))
#define CPASYNC16Z(sa, g, sz) asm volatile("cp.async.cg.shared.global [%0], [%1], 16, %2;" :: "r"(sa), "l"(g), "r"(sz))
#define CPCOMMIT() asm volatile("cp.async.commit_group;")
#define CPWAIT(n) asm volatile("cp.async.wait_group %0;" :: "n"(n))

__device__ __forceinline__ void mma_tf32(float c[4], const uint32_t a[4], const uint32_t b[2]) {
    asm volatile(
        "mma.sync.aligned.m16n8k8.row.col.f32.tf32.tf32.f32 "
        "{%0,%1,%2,%3}, {%4,%5,%6,%7}, {%8,%9}, {%0,%1,%2,%3};"
        : "+f"(c[0]), "+f"(c[1]), "+f"(c[2]), "+f"(c[3])
        : "r"(a[0]), "r"(a[1]), "r"(a[2]), "r"(a[3]), "r"(b[0]), "r"(b[1]));
}

#define SIG(x) (1.f / (1.f + __expf(-(x))))

// ========== precompute GEMM (k_pre only): 128x128 tiles, depth-2 =============
__device__ __forceinline__ void gemm_pre(
    int ctam, int ctan,
    const float* __restrict__ Ag, const uint32_t* __restrict__ Bt,
    const float* __restrict__ e1, const float* __restrict__ e2,
    float* __restrict__ Cout, int K, char* dyn)
{
    float* As = (float*)dyn;
    uint32_t* Bs = (uint32_t*)(dyn + 36864);
    const int tid = threadIdx.x;
    const int lane = tid & 31;
    const int wid = tid >> 5;
    const int wm = wid & 3;
    const int wn = wid >> 2;
    const int tg = lane & 3;
    const int gp = lane >> 2;

    float acc[2][8][4];
#pragma unroll
    for (int i = 0; i < 2; ++i)
#pragma unroll
        for (int j = 0; j < 8; ++j)
#pragma unroll
            for (int k = 0; k < 4; ++k) acc[i][j][k] = 0.f;

    const int nc = K >> 5;
    auto stage = [&](int buf, int kc) {
#pragma unroll
        for (int it = 0; it < 4; ++it) {
            int slot = it * 256 + tid;
            int row = slot >> 3;
            int cc = (slot & 7) << 2;
            uint32_t sa = cvta_s(As + buf * 4608 + row * 36 + cc);
            int m = ctam * 128 + row;
            int t_ = m >> 8;
            int b_ = m & 255;
            const float* ga = (t_ == 0) ? Ag : Ag + ((size_t)b_ * TT + t_) * II + kc + cc;
            int sz = (t_ == 0) ? 0 : 16;
            CPASYNC16Z(sa, ga, sz);
            uint32_t sb = cvta_s(Bs + buf * 4608 + row * 36 + cc);
            CPASYNC16(sb, Bt + (size_t)(ctan * 128 + row) * K + kc + cc);
        }
    };

    stage(0, 0);
    CPCOMMIT();
    for (int c = 0; c < nc; ++c) {
        if (c + 1 < nc) stage((c + 1) & 1, (c + 1) * 32);
        CPCOMMIT();
        CPWAIT(1);
        __syncthreads();
        const float* Af = As + (c & 1) * 4608;
        const uint32_t* Bf = Bs + (c & 1) * 4608;
#pragma unroll
        for (int ks = 0; ks < 4; ++ks) {
            uint32_t a[2][4], b[8][2];
#pragma unroll
            for (int mt = 0; mt < 2; ++mt) {
                int r = wm * 32 + mt * 16 + gp;
                a[mt][0] = f2tf32(Af[r * 36 + ks * 8 + tg]);
                a[mt][1] = f2tf32(Af[(r + 8) * 36 + ks * 8 + tg]);
                a[mt][2] = f2tf32(Af[r * 36 + ks * 8 + tg + 4]);
                a[mt][3] = f2tf32(Af[(r + 8) * 36 + ks * 8 + tg + 4]);
            }
#pragma unroll
            for (int nt = 0; nt < 8; ++nt) {
                int n = wn * 64 + nt * 8 + gp;
                b[nt][0] = Bf[n * 36 + ks * 8 + tg];
                b[nt][1] = Bf[n * 36 + ks * 8 + tg + 4];
            }
#pragma unroll
            for (int mt = 0; mt < 2; ++mt)
#pragma unroll
                for (int nt = 0; nt < 8; ++nt)
                    mma_tf32(acc[mt][nt], a[mt], b[nt]);
        }
        __syncthreads();
    }
#pragma unroll
    for (int mt = 0; mt < 2; ++mt)
#pragma unroll
        for (int nt = 0; nt < 8; ++nt) {
            int gm0 = ctam * 128 + wm * 32 + mt * 16 + gp;
            int gn = ctan * 128 + wn * 64 + nt * 8 + tg * 2;
#pragma unroll
            for (int half = 0; half < 2; ++half) {
                int gm = gm0 + half * 8;
                float v0 = acc[mt][nt][half * 2 + 0] + e1[gn] + e2[gn];
                float v1 = acc[mt][nt][half * 2 + 1] + e1[gn + 1] + e2[gn + 1];
                *(float2*)(Cout + (size_t)gm * G4 + gn) = make_float2(v0, v1);
            }
        }
}

// ========== fused gates GEMM + LSTM cell (fragment-permuted tf32) =============
// Tile: 64 M x (4 gates x 32 hidden cols). grid 4 x 32 = 128 CTAs.
// K-chunk 64, depth-2. smem: As u32 [2][64][72] @0 (36864 B),
//                            Bs u32 [2][128][72] @36864 (73728 B) -> 110592 total
// epilogue reuse: ep fp32 [64][132] @0 (33792 B)
__device__ __forceinline__ void gatescell_dev(
    int ctam, int ctan,
    const uint32_t* __restrict__ hA,   // h_{t-1}, tf32 permuted
    const float* __restrict__ Xg,      // d_Xg + t*BB*G4
    float* __restrict__ hOut,          // h_t fp32
    uint32_t* __restrict__ hOut32,     // h_t tf32 permuted
    char* dyn)
{
    uint32_t* As = (uint32_t*)dyn;
    uint32_t* Bs = (uint32_t*)(dyn + 36864);
    const int tid = threadIdx.x;
    const int lane = tid & 31;
    const int wid = tid >> 5;
    const int wm = wid & 1;      // 2 M halves of 32 rows
    const int g = wid >> 1;      // warp owns one gate (0..3)
    const int tg = lane & 3;
    const int gp = lane >> 2;
    const int q0 = ctan * 32;
    const int m0 = ctam * 64;

    float acc[2][4][4];
#pragma unroll
    for (int i = 0; i < 2; ++i)
#pragma unroll
        for (int j = 0; j < 4; ++j)
#pragma unroll
            for (int k = 0; k < 4; ++k) acc[i][j][k] = 0.f;

    auto stage = [&](int buf, int kc) {
        // A: 64x64 u32 = 1024 x 16B, 4 per thread
#pragma unroll
        for (int it = 0; it < 4; ++it) {
            int slot = it * 256 + tid;
            int row = slot >> 4;
            int cc = (slot & 15) << 2;
            CPASYNC16(cvta_s(As + buf * 4608 + row * 72 + cc),
                      hA + (size_t)(m0 + row) * HH + kc + cc);
        }
        // B: 128x64 u32 = 2048 x 16B, 8 per thread; rows gather 4 gate blocks
#pragma unroll
        for (int it = 0; it < 8; ++it) {
            int slot = it * 256 + tid;
            int row = slot >> 4;
            int cc = (slot & 15) << 2;
            int wr = (row >> 5) * HH + q0 + (row & 31);
            CPASYNC16(cvta_s(Bs + buf * 9216 + row * 72 + cc),
                      d_Whh_t + (size_t)wr * HH + kc + cc);
        }
    };

    stage(0, 0); CPCOMMIT();
    const int nc = 16;  // K=1024 / 64
    for (int c = 0; c < nc; ++c) {
        if (c + 1 < nc) stage((c + 1) & 1, (c + 1) * 64);
        CPCOMMIT();
        CPWAIT(1);
        __syncthreads();
        const uint32_t* Af = As + (c & 1) * 4608;
        const uint32_t* Bf = Bs + (c & 1) * 9216;
#pragma unroll
        for (int ks = 0; ks < 8; ++ks) {
            uint32_t a[2][4], b[4][2];
#pragma unroll
            for (int mt = 0; mt < 2; ++mt) {
                int r = wm * 32 + mt * 16 + gp;
                uint2 lo = *(const uint2*)(Af + r * 72 + ks * 8 + tg * 2);
                uint2 hi = *(const uint2*)(Af + (r + 8) * 72 + ks * 8 + tg * 2);
                a[mt][0] = lo.x; a[mt][2] = lo.y;
                a[mt][1] = hi.x; a[mt][3] = hi.y;
            }
#pragma unroll
            for (int nt = 0; nt < 4; ++nt) {
                int n = g * 32 + nt * 8 + gp;
                uint2 v = *(const uint2*)(Bf + n * 72 + ks * 8 + tg * 2);
                b[nt][0] = v.x; b[nt][1] = v.y;
            }
#pragma unroll
            for (int mt = 0; mt < 2; ++mt)
#pragma unroll
                for (int nt = 0; nt < 4; ++nt)
                    mma_tf32(acc[mt][nt], a[mt], b[nt]);
        }
        __syncthreads();
    }

    // gate exchange: ep[row 64][n 128], n = g*32 + qq, stride 132
    float* ep = (float*)dyn;
    __syncthreads();
#pragma unroll
    for (int mt = 0; mt < 2; ++mt)
#pragma unroll
        for (int nt = 0; nt < 4; ++nt) {
            int r0 = wm * 32 + mt * 16 + gp;
            int col = g * 32 + nt * 8 + tg * 2;
            *(float2*)(ep + r0 * 132 + col) = make_float2(acc[mt][nt][0], acc[mt][nt][1]);
            *(float2*)(ep + (r0 + 8) * 132 + col) = make_float2(acc[mt][nt][2], acc[mt][nt][3]);
        }
    __syncthreads();

    // cell: 2048 elems, 8 per thread
#pragma unroll
    for (int k = 0; k < 8; ++k) {
        int idx = k * 256 + tid;
        int row = idx >> 5;
        int qq = idx & 31;
        int b = m0 + row;
        int q = q0 + qq;
        size_t xb = (size_t)b * G4 + q;
        float vi = ep[row * 132 + qq]        + Xg[xb];
        float vf = ep[row * 132 + 32 + qq]   + Xg[xb + HH];
        float vg = ep[row * 132 + 64 + qq]   + Xg[xb + 2 * HH];
        float vo = ep[row * 132 + 96 + qq]   + Xg[xb + 3 * HH];
        size_t hb = (size_t)b * HH + q;
        float c_old = d_c[hb];
        float c_new = SIG(vf) * c_old + SIG(vi) * tanhf(vg);
        float h_new = SIG(vo) * tanhf(c_new);
        d_c[hb] = c_new;
        hOut[hb] = h_new;
        hOut32[(size_t)b * HH + kperm(q)] = f2tf32(h_new);
    }
}

// ========== FC split-K partial GEMM ==========================================
// Tile 128M x 64N, K-slice 512 (16 chunks), depth-3. grid 2x4x4 = 32 CTAs.
// smem: Af fp32 [3][128][36] @0 (55296), Bf u32 [3][64][36] @55296 (27648)
__device__ __forceinline__ void fcpart_dev(
    int ctam, int ctan, int kslice,
    const float* __restrict__ u,       // [256][2048]
    float* __restrict__ part)          // [256][256]
{
    extern __shared__ char dyn[];
    float* Af = (float*)dyn;
    uint32_t* Bf = (uint32_t*)(dyn + 55296);
    const int tid = threadIdx.x;
    const int lane = tid & 31;
    const int wid = tid >> 5;
    const int wm = wid & 3;
    const int wn = wid >> 2;
    const int tg = lane & 3;
    const int gp = lane >> 2;
    const int k0 = kslice * 512;

    float acc[2][4][4];
#pragma unroll
    for (int i = 0; i < 2; ++i)
#pragma unroll
        for (int j = 0; j < 4; ++j)
#pragma unroll
            for (int k = 0; k < 4; ++k) acc[i][j][k] = 0.f;

    auto stage = [&](int buf, int kc) {
#pragma unroll
        for (int it = 0; it < 4; ++it) {
            int slot = it * 256 + tid;
            int row = slot >> 3;
            int cc = (slot & 7) << 2;
            CPASYNC16(cvta_s(Af + buf * 4608 + row * 36 + cc),
                      u + (size_t)(ctam * 128 + row) * (2 * HH) + k0 + kc + cc);
        }
#pragma unroll
        for (int it = 0; it < 2; ++it) {
            int slot = it * 256 + tid;
            int row = slot >> 3;
            int cc = (slot & 7) << 2;
            CPASYNC16(cvta_s(Bf + buf * 2304 + row * 36 + cc),
                      d_Wfc_t + (size_t)(ctan * 64 + row) * (2 * HH) + k0 + kc + cc);
        }
    };

    stage(0, 0); CPCOMMIT();
    stage(1, 32); CPCOMMIT();
    const int nc = 16;
    for (int c = 0; c < nc; ++c) {
        if (c + 2 < nc) stage((c + 2) % 3, (c + 2) * 32);
        CPCOMMIT();
        CPWAIT(2);
        __syncthreads();
        const float* A = Af + (c % 3) * 4608;
        const uint32_t* B = Bf + (c % 3) * 2304;
#pragma unroll
        for (int kk = 0; kk < 4; ++kk) {
            uint32_t a[2][4], b[4][2];
#pragma unroll
            for (int mt = 0; mt < 2; ++mt) {
                int r = wm * 32 + mt * 16 + gp;
                a[mt][0] = f2tf32(A[r * 36 + kk * 8 + tg]);
                a[mt][1] = f2tf32(A[(r + 8) * 36 + kk * 8 + tg]);
                a[mt][2] = f2tf32(A[r * 36 + kk * 8 + tg + 4]);
                a[mt][3] = f2tf32(A[(r + 8) * 36 + kk * 8 + tg + 4]);
            }
#pragma unroll
            for (int nt = 0; nt < 4; ++nt) {
                int n = wn * 32 + nt * 8 + gp;
                b[nt][0] = B[n * 36 + kk * 8 + tg];
                b[nt][1] = B[n * 36 + kk * 8 + tg + 4];
            }
#pragma unroll
            for (int mt = 0; mt < 2; ++mt)
#pragma unroll
                for (int nt = 0; nt < 4; ++nt)
                    mma_tf32(acc[mt][nt], a[mt], b[nt]);
        }
        __syncthreads();
    }
#pragma unroll
    for (int mt = 0; mt < 2; ++mt)
#pragma unroll
        for (int nt = 0; nt < 4; ++nt) {
            int gm0 = ctam * 128 + wm * 32 + mt * 16 + gp;
            int gn = ctan * 64 + wn * 32 + nt * 8 + tg * 2;
            *(float2*)(part + (size_t)gm0 * OO + gn) =
                make_float2(acc[mt][nt][0], acc[mt][nt][1]);
            *(float2*)(part + (size_t)(gm0 + 8) * OO + gn) =
                make_float2(acc[mt][nt][2], acc[mt][nt][3]);
        }
}

// ========== attention (cp.async pipelined single-pass softmax) ================
__device__ __forceinline__ void attn_dev(int b, int tatt, const float* __restrict__ enc,
                                         const float* __restrict__ hcur,
                                         float* __restrict__ out, int par, char* dyn,
                                         float* s_scores, float* s_m, float* s_l)
{
    float* es = (float*)dyn;
    const int tid = threadIdx.x;
    const int lane = tid & 31;
    const int w = tid >> 5;

    const float* hb = hcur + (size_t)b * HH;
    float hreg[32];
#pragma unroll
    for (int i = 0; i < 32; ++i) hreg[i] = hb[i * 32 + lane];

    const float* encb = enc + (size_t)b * SS * HH;
#pragma unroll
    for (int p = 0; p < 3; ++p) {
        const float* gsrc = encb + (size_t)(w * 16 + p) * HH;
        float* sb = es + ((size_t)(p % 3) * 8 + w) * 1024;
#pragma unroll
        for (int q = 0; q < 8; ++q)
            CPASYNC16(cvta_s(sb + q * 128 + lane * 4), gsrc + q * 128 + lane * 4);
        CPCOMMIT();
    }

    float m = -1e30f, l = 0.f;
    float ctx[32];
#pragma unroll
    for (int i = 0; i < 32; ++i) ctx[i] = 0.f;

    for (int j = 0; j < 16; ++j) {
        CPWAIT(2);
        __syncwarp();
        const float* e = es + ((size_t)(j % 3) * 8 + w) * 1024;
        float dot = 0.f;
#pragma unroll
        for (int i = 0; i < 32; ++i) dot += hreg[i] * e[i * 32 + lane];
#pragma unroll
        for (int o = 16; o; o >>= 1) dot += __shfl_xor_sync(0xffffffffu, dot, o);
        if (lane == 0) s_scores[w * 16 + j] = dot;

        float nm = fmaxf(m, dot);
        float al = __expf(m - nm);
        float p = __expf(dot - nm);
        l = l * al + p;
#pragma unroll
        for (int i = 0; i < 32; ++i) ctx[i] = ctx[i] * al + p * e[i * 32 + lane];
        m = nm;
        __syncwarp();
        if (j + 3 < 16) {
            const float* gsrc = encb + (size_t)(w * 16 + j + 3) * HH;
            float* sb = es + ((size_t)(j % 3) * 8 + w) * 1024;
#pragma unroll
            for (int q = 0; q < 8; ++q)
                CPASYNC16(cvta_s(sb + q * 128 + lane * 4), gsrc + q * 128 + lane * 4);
        }
        CPCOMMIT();
    }
    CPWAIT(0);
    if (lane == 0) { s_m[w] = m; s_l[w] = l; }
    __syncthreads();

    float M = -1e30f;
#pragma unroll
    for (int i = 0; i < 8; ++i) M = fmaxf(M, s_m[i]);
    float L = 0.f;
#pragma unroll
    for (int i = 0; i < 8; ++i) L += s_l[i] * __expf(s_m[i] - M);

    float sc = __expf(m - M);
    float* cs = es + (size_t)w * 1024;
#pragma unroll
    for (int i = 0; i < 32; ++i) cs[i * 32 + lane] = ctx[i] * sc;
    __syncthreads();

    float* ubuf = d_u[par];
    for (int kk = tid; kk < HH; kk += 256) {
        float sum = 0.f;
#pragma unroll
        for (int ww = 0; ww < 8; ++ww) sum += es[(size_t)ww * 1024 + kk];
        ubuf[(size_t)b * 2 * HH + kk] = sum / L;
        ubuf[(size_t)b * 2 * HH + HH + kk] = hb[kk];
    }
    if (tid < SS) {
        float p = __expf(s_scores[tid] - M) / L;
        out[(size_t)BB * TT * OO + (size_t)b * TT * SS + (size_t)tatt * SS + tid] = p;
    }
}

// ---------------- kernels -----------------------------------------------------
__global__ void k_init() {
    int g = blockIdx.x * 256 + threadIdx.x;  // 65536 float4s per array
    float4 z = make_float4(0.f, 0.f, 0.f, 0.f);
    ((float4*)d_h[1])[g] = z;
    ((float4*)d_ht32[1])[g] = z;
    ((float4*)d_c)[g] = z;
}

__global__ void __launch_bounds__(256) k_convert(const float* __restrict__ Wih,
                                                 const float* __restrict__ Whh,
                                                 const float* __restrict__ Wfc) {
    int g = blockIdx.x * 256 + threadIdx.x;
    int stride = gridDim.x * 256;
    for (int i = g; i < G4 * II; i += stride) d_Wih_t[i] = f2tf32(Wih[i]);
    for (int i = g; i < G4 * HH; i += stride) {
        int n = i >> 10;
        int k = i & 1023;
        d_Whh_t[(size_t)n * HH + kperm(k)] = f2tf32(Whh[i]);
    }
    for (int i = g; i < OO * 2 * HH; i += stride) d_Wfc_t[i] = f2tf32(Wfc[i]);
}

__global__ void __launch_bounds__(256, 2) k_pre(const float* __restrict__ st,
                                                const float* __restrict__ bih,
                                                const float* __restrict__ bhh) {
    extern __shared__ char dyn[];
    gemm_pre(blockIdx.x >> 5, blockIdx.x & 31, st, d_Wih_t, bih, bhh, d_Xg, II, dyn);
}

__global__ void __launch_bounds__(256, 2) kA(int t, int nG, int nA, int nP,
                                             const float* __restrict__ enc,
                                             const float* __restrict__ bfc,
                                             float* __restrict__ out) {
    extern __shared__ char dyn[];
    __shared__ float s_scores[SS];
    __shared__ float s_m[8], s_l[8];
    int bid = blockIdx.x;
    if (bid < nG) {
        gatescell_dev(bid >> 5, bid & 31,
                      d_ht32[(t + 1) & 1], d_Xg + (size_t)t * BB * G4,
                      d_h[t & 1], d_ht32[t & 1], dyn);
    } else if (bid < nG + nA) {
        // attention for step t-1: each CTA handles 2 batches
        int ta = t - 1;
        int b0 = (bid - nG) * 2;
#pragma unroll
        for (int sub = 0; sub < 2; ++sub) {
            attn_dev(b0 + sub, ta, enc, d_h[ta & 1], out, ta & 1, dyn,
                     s_scores, s_m, s_l);
            __syncthreads();
        }
    } else if (bid < nG + nA + nP) {
        int f = bid - nG - nA;     // 0..31
        int tfc = t - 2;
        int ks = f & 3;
        int ctan = (f >> 2) & 3;
        int ctam = f >> 4;
        fcpart_dev(ctam, ctan, ks, d_u[tfc & 1], d_fcp[tfc & 1][ks]);
    } else {
        int tr = t - 3;
        const float* p0 = d_fcp[tr & 1][0];
        const float* p1 = d_fcp[tr & 1][1];
        const float* p2 = d_fcp[tr & 1][2];
        const float* p3 = d_fcp[tr & 1][3];
        int bidr = bid - nG - nA - nP;  // 0..15
        for (int e = bidr * 256 + threadIdx.x; e < BB * OO; e += 16 * 256) {
            int b = e >> 8;
            int o = e & 255;
            float v = p0[e] + p1[e] + p2[e] + p3[e] + bfc[o];
            out[(size_t)b * TT * OO + (size_t)tr * OO + o] = v;
        }
    }
}

// ---------------- launch --------------------------------------------------------
extern "C" void kernel_launch(void* const* d_in, const int* in_sizes, int n_in,
                              void* d_out, int out_size) {
    const float* st  = (const float*)d_in[0];
    const float* enc = (const float*)d_in[1];
    const float* Wih = (const float*)d_in[2];
    const float* Whh = (const float*)d_in[3];
    const float* bih = (const float*)d_in[4];
    const float* bhh = (const float*)d_in[5];
    const float* Wfc = (const float*)d_in[6];
    const float* bfc = (const float*)d_in[7];
    float* out = (float*)d_out;

    static const int DYN_GEMM = 73728;
    static const int DYN_KA = 110592;   // gates: 36864(A) + 73728(B); attn needs 98304
    cudaFuncSetAttribute(k_pre, cudaFuncAttributeMaxDynamicSharedMemorySize, DYN_GEMM);
    cudaFuncSetAttribute(kA, cudaFuncAttributeMaxDynamicSharedMemorySize, DYN_KA);

    k_init<<<256, 256>>>();                       // 0
    k_convert<<<592, 256>>>(Wih, Whh, Wfc);       // 1
    k_pre<<<2048, 256, DYN_GEMM>>>(st, bih, bhh); // 2

    // 3: kA(0), 4: kA(1), 5: kA(2) <- ncu -s 5 profiles mixed gates+attn+fc
    for (int t = 0; t <= TT + 2; ++t) {
        int nG = (t < TT) ? 128 : 0;                     // gates+cell step t
        int nA = (t >= 1 && t <= TT) ? 128 : 0;          // attention step t-1 (2 batches/CTA)
        int nP = (t >= 2 && t <= TT + 1) ? 32 : 0;       // fc partials step t-2
        int nR = (t >= 3) ? 16 : 0;                      // fc reduce step t-3
        kA<<<nG + nA + nP + nR, 256, DYN_KA>>>(t, nG, nA, nP, enc, bfc, out);
    }
}

// round 6
// speedup vs baseline: 1.2531x; 1.0014x over previous
#include <cuda_runtime.h>
#include <math.h>
#include <stdint.h>

#define BB 256
#define TT 32
#define SS 128
#define II 256
#define HH 1024
#define OO 256
#define G4 4096

// ---------------- scratch (static device globals; no allocation) ------------
__device__ float d_Xg[(size_t)TT * BB * G4];   // [T][B][4H] input gates + biases
__device__ float d_h[2][BB * HH];              // double-buffered hidden state (fp32)
__device__ uint32_t d_ht32[2][BB * HH];        // double-buffered hidden, tf32 fragment-permuted
__device__ float d_c[BB * HH];
__device__ float d_u[2][BB * 2 * HH];          // double-buffered [ctx|h] for FC
__device__ float d_fcp[2][4][BB * OO];         // split-K FC partials
__device__ uint32_t d_Wih_t[G4 * II];          // tf32 (plain layout)
__device__ uint32_t d_Whh_t[(size_t)G4 * HH];  // tf32, fragment-permuted within k8 groups
__device__ uint32_t d_Wfc_t[OO * 2 * HH];      // tf32 (plain layout)

// ---------------- helpers ----------------------------------------------------
__device__ __forceinline__ uint32_t f2tf32(float x) {
    uint32_t r;
    asm("cvt.rna.tf32.f32 %0, %1;" : "=r"(r) : "f"(x));
    return r;
}
__device__ __forceinline__ uint32_t cvta_s(const void* p) {
    return (uint32_t)__cvta_generic_to_shared(p);
}
// permute k within its 8-group so (k, k+4) become adjacent: j = 2*(k&3) + ((k>>2)&1)
__device__ __forceinline__ int kperm(int k) {
    return (k & ~7) + ((k & 3) << 1) + ((k >> 2) & 1);
}
#define CPASYNC16(sa, g) asm volatile("cp.async.cg.shared.global [%0], [%1], 16;" :: "r"(sa), "l"(g))
#define CPASYNC16Z(sa, g, sz) asm volatile("cp.async.cg.shared.global [%0], [%1], 16, %2;" :: "r"(sa), "l"(g), "r"(sz))
#define CPCOMMIT() asm volatile("cp.async.commit_group;")
#define CPWAIT(n) asm volatile("cp.async.wait_group %0;" :: "n"(n))

__device__ __forceinline__ void mma_tf32(float c[4], const uint32_t a[4], const uint32_t b[2]) {
    asm volatile(
        "mma.sync.aligned.m16n8k8.row.col.f32.tf32.tf32.f32 "
        "{%0,%1,%2,%3}, {%4,%5,%6,%7}, {%8,%9}, {%0,%1,%2,%3};"
        : "+f"(c[0]), "+f"(c[1]), "+f"(c[2]), "+f"(c[3])
        : "r"(a[0]), "r"(a[1]), "r"(a[2]), "r"(a[3]), "r"(b[0]), "r"(b[1]));
}

#define SIG(x) (1.f / (1.f + __expf(-(x))))

// ========== precompute GEMM (k_pre only): 128x128 tiles, depth-2 =============
__device__ __forceinline__ void gemm_pre(
    int ctam, int ctan,
    const float* __restrict__ Ag, const uint32_t* __restrict__ Bt,
    const float* __restrict__ e1, const float* __restrict__ e2,
    float* __restrict__ Cout, int K, char* dyn)
{
    float* As = (float*)dyn;
    uint32_t* Bs = (uint32_t*)(dyn + 36864);
    const int tid = threadIdx.x;
    const int lane = tid & 31;
    const int wid = tid >> 5;
    const int wm = wid & 3;
    const int wn = wid >> 2;
    const int tg = lane & 3;
    const int gp = lane >> 2;

    float acc[2][8][4];
#pragma unroll
    for (int i = 0; i < 2; ++i)
#pragma unroll
        for (int j = 0; j < 8; ++j)
#pragma unroll
            for (int k = 0; k < 4; ++k) acc[i][j][k] = 0.f;

    const int nc = K >> 5;
    auto stage = [&](int buf, int kc) {
#pragma unroll
        for (int it = 0; it < 4; ++it) {
            int slot = it * 256 + tid;
            int row = slot >> 3;
            int cc = (slot & 7) << 2;
            uint32_t sa = cvta_s(As + buf * 4608 + row * 36 + cc);
            int m = ctam * 128 + row;
            int t_ = m >> 8;
            int b_ = m & 255;
            const float* ga = (t_ == 0) ? Ag : Ag + ((size_t)b_ * TT + t_) * II + kc + cc;
            int sz = (t_ == 0) ? 0 : 16;
            CPASYNC16Z(sa, ga, sz);
            uint32_t sb = cvta_s(Bs + buf * 4608 + row * 36 + cc);
            CPASYNC16(sb, Bt + (size_t)(ctan * 128 + row) * K + kc + cc);
        }
    };

    stage(0, 0);
    CPCOMMIT();
    for (int c = 0; c < nc; ++c) {
        if (c + 1 < nc) stage((c + 1) & 1, (c + 1) * 32);
        CPCOMMIT();
        CPWAIT(1);
        __syncthreads();
        const float* Af = As + (c & 1) * 4608;
        const uint32_t* Bf = Bs + (c & 1) * 4608;
#pragma unroll
        for (int ks = 0; ks < 4; ++ks) {
            uint32_t a[2][4], b[8][2];
#pragma unroll
            for (int mt = 0; mt < 2; ++mt) {
                int r = wm * 32 + mt * 16 + gp;
                a[mt][0] = f2tf32(Af[r * 36 + ks * 8 + tg]);
                a[mt][1] = f2tf32(Af[(r + 8) * 36 + ks * 8 + tg]);
                a[mt][2] = f2tf32(Af[r * 36 + ks * 8 + tg + 4]);
                a[mt][3] = f2tf32(Af[(r + 8) * 36 + ks * 8 + tg + 4]);
            }
#pragma unroll
            for (int nt = 0; nt < 8; ++nt) {
                int n = wn * 64 + nt * 8 + gp;
                b[nt][0] = Bf[n * 36 + ks * 8 + tg];
                b[nt][1] = Bf[n * 36 + ks * 8 + tg + 4];
            }
#pragma unroll
            for (int mt = 0; mt < 2; ++mt)
#pragma unroll
                for (int nt = 0; nt < 8; ++nt)
                    mma_tf32(acc[mt][nt], a[mt], b[nt]);
        }
        __syncthreads();
    }
#pragma unroll
    for (int mt = 0; mt < 2; ++mt)
#pragma unroll
        for (int nt = 0; nt < 8; ++nt) {
            int gm0 = ctam * 128 + wm * 32 + mt * 16 + gp;
            int gn = ctan * 128 + wn * 64 + nt * 8 + tg * 2;
#pragma unroll
            for (int half = 0; half < 2; ++half) {
                int gm = gm0 + half * 8;
                float v0 = acc[mt][nt][half * 2 + 0] + e1[gn] + e2[gn];
                float v1 = acc[mt][nt][half * 2 + 1] + e1[gn + 1] + e2[gn + 1];
                *(float2*)(Cout + (size_t)gm * G4 + gn) = make_float2(v0, v1);
            }
        }
}

// ---- gates fragment loader (permuted tf32: uint2 = (k, k+4) pair) -----------
__device__ __forceinline__ void gates_ldfrag(
    const uint32_t* __restrict__ Af, const uint32_t* __restrict__ Bf,
    int wm, int g, int gp, int tg, int ks,
    uint32_t a[2][4], uint32_t b[4][2])
{
#pragma unroll
    for (int mt = 0; mt < 2; ++mt) {
        int r = wm * 32 + mt * 16 + gp;
        uint2 lo = *(const uint2*)(Af + r * 72 + ks * 8 + tg * 2);
        uint2 hi = *(const uint2*)(Af + (r + 8) * 72 + ks * 8 + tg * 2);
        a[mt][0] = lo.x; a[mt][2] = lo.y;
        a[mt][1] = hi.x; a[mt][3] = hi.y;
    }
#pragma unroll
    for (int nt = 0; nt < 4; ++nt) {
        int n = g * 32 + nt * 8 + gp;
        uint2 v = *(const uint2*)(Bf + n * 72 + ks * 8 + tg * 2);
        b[nt][0] = v.x; b[nt][1] = v.y;
    }
}

// ========== fused gates GEMM + LSTM cell (fragment-permuted tf32) =============
// Tile: 64 M x (4 gates x 32 hidden cols). grid 4 x 32 = 128 CTAs.
// K-chunk 64, depth-2. smem: As u32 [2][64][72] @0 (36864 B),
//                            Bs u32 [2][128][72] @36864 (73728 B) -> 110592 total
// Inner ks loop is register double-buffered (fragments prefetched one ks ahead).
__device__ __forceinline__ void gatescell_dev(
    int ctam, int ctan,
    const uint32_t* __restrict__ hA,   // h_{t-1}, tf32 permuted
    const float* __restrict__ Xg,      // d_Xg + t*BB*G4
    float* __restrict__ hOut,          // h_t fp32
    uint32_t* __restrict__ hOut32,     // h_t tf32 permuted
    char* dyn)
{
    uint32_t* As = (uint32_t*)dyn;
    uint32_t* Bs = (uint32_t*)(dyn + 36864);
    const int tid = threadIdx.x;
    const int lane = tid & 31;
    const int wid = tid >> 5;
    const int wm = wid & 1;      // 2 M halves of 32 rows
    const int g = wid >> 1;      // warp owns one gate (0..3)
    const int tg = lane & 3;
    const int gp = lane >> 2;
    const int q0 = ctan * 32;
    const int m0 = ctam * 64;

    float acc[2][4][4];
#pragma unroll
    for (int i = 0; i < 2; ++i)
#pragma unroll
        for (int j = 0; j < 4; ++j)
#pragma unroll
            for (int k = 0; k < 4; ++k) acc[i][j][k] = 0.f;

    auto stage = [&](int buf, int kc) {
        // A: 64x64 u32 = 1024 x 16B, 4 per thread
#pragma unroll
        for (int it = 0; it < 4; ++it) {
            int slot = it * 256 + tid;
            int row = slot >> 4;
            int cc = (slot & 15) << 2;
            CPASYNC16(cvta_s(As + buf * 4608 + row * 72 + cc),
                      hA + (size_t)(m0 + row) * HH + kc + cc);
        }
        // B: 128x64 u32 = 2048 x 16B, 8 per thread; rows gather 4 gate blocks
#pragma unroll
        for (int it = 0; it < 8; ++it) {
            int slot = it * 256 + tid;
            int row = slot >> 4;
            int cc = (slot & 15) << 2;
            int wr = (row >> 5) * HH + q0 + (row & 31);
            CPASYNC16(cvta_s(Bs + buf * 9216 + row * 72 + cc),
                      d_Whh_t + (size_t)wr * HH + kc + cc);
        }
    };

    stage(0, 0); CPCOMMIT();
    const int nc = 16;  // K=1024 / 64
    for (int c = 0; c < nc; ++c) {
        if (c + 1 < nc) stage((c + 1) & 1, (c + 1) * 64);
        CPCOMMIT();
        CPWAIT(1);
        __syncthreads();
        const uint32_t* Af = As + (c & 1) * 4608;
        const uint32_t* Bf = Bs + (c & 1) * 9216;

        // register double-buffered fragment pipeline over 8 ks groups
        uint32_t a[2][2][4], b[2][4][2];
        gates_ldfrag(Af, Bf, wm, g, gp, tg, 0, a[0], b[0]);
#pragma unroll
        for (int ks = 0; ks < 8; ++ks) {
            if (ks < 7)
                gates_ldfrag(Af, Bf, wm, g, gp, tg, ks + 1, a[(ks + 1) & 1], b[(ks + 1) & 1]);
            const int s = ks & 1;
#pragma unroll
            for (int mt = 0; mt < 2; ++mt)
#pragma unroll
                for (int nt = 0; nt < 4; ++nt)
                    mma_tf32(acc[mt][nt], a[s][mt], b[s][nt]);
        }
        __syncthreads();
    }

    // gate exchange: ep[row 64][n 128], n = g*32 + qq, stride 132
    float* ep = (float*)dyn;
    __syncthreads();
#pragma unroll
    for (int mt = 0; mt < 2; ++mt)
#pragma unroll
        for (int nt = 0; nt < 4; ++nt) {
            int r0 = wm * 32 + mt * 16 + gp;
            int col = g * 32 + nt * 8 + tg * 2;
            *(float2*)(ep + r0 * 132 + col) = make_float2(acc[mt][nt][0], acc[mt][nt][1]);
            *(float2*)(ep + (r0 + 8) * 132 + col) = make_float2(acc[mt][nt][2], acc[mt][nt][3]);
        }
    __syncthreads();

    // cell: 2048 elems, 8 per thread
#pragma unroll
    for (int k = 0; k < 8; ++k) {
        int idx = k * 256 + tid;
        int row = idx >> 5;
        int qq = idx & 31;
        int b = m0 + row;
        int q = q0 + qq;
        size_t xb = (size_t)b * G4 + q;
        float vi = ep[row * 132 + qq]        + Xg[xb];
        float vf = ep[row * 132 + 32 + qq]   + Xg[xb + HH];
        float vg = ep[row * 132 + 64 + qq]   + Xg[xb + 2 * HH];
        float vo = ep[row * 132 + 96 + qq]   + Xg[xb + 3 * HH];
        size_t hb = (size_t)b * HH + q;
        float c_old = d_c[hb];
        float c_new = SIG(vf) * c_old + SIG(vi) * tanhf(vg);
        float h_new = SIG(vo) * tanhf(c_new);
        d_c[hb] = c_new;
        hOut[hb] = h_new;
        hOut32[(size_t)b * HH + kperm(q)] = f2tf32(h_new);
    }
}

// ========== FC split-K partial GEMM ==========================================
// Tile 128M x 64N, K-slice 512 (16 chunks), depth-3. grid 2x4x4 = 32 CTAs.
// smem: Af fp32 [3][128][36] @0 (55296), Bf u32 [3][64][36] @55296 (27648)
__device__ __forceinline__ void fcpart_dev(
    int ctam, int ctan, int kslice,
    const float* __restrict__ u,       // [256][2048]
    float* __restrict__ part)          // [256][256]
{
    extern __shared__ char dyn[];
    float* Af = (float*)dyn;
    uint32_t* Bf = (uint32_t*)(dyn + 55296);
    const int tid = threadIdx.x;
    const int lane = tid & 31;
    const int wid = tid >> 5;
    const int wm = wid & 3;
    const int wn = wid >> 2;
    const int tg = lane & 3;
    const int gp = lane >> 2;
    const int k0 = kslice * 512;

    float acc[2][4][4];
#pragma unroll
    for (int i = 0; i < 2; ++i)
#pragma unroll
        for (int j = 0; j < 4; ++j)
#pragma unroll
            for (int k = 0; k < 4; ++k) acc[i][j][k] = 0.f;

    auto stage = [&](int buf, int kc) {
#pragma unroll
        for (int it = 0; it < 4; ++it) {
            int slot = it * 256 + tid;
            int row = slot >> 3;
            int cc = (slot & 7) << 2;
            CPASYNC16(cvta_s(Af + buf * 4608 + row * 36 + cc),
                      u + (size_t)(ctam * 128 + row) * (2 * HH) + k0 + kc + cc);
        }
#pragma unroll
        for (int it = 0; it < 2; ++it) {
            int slot = it * 256 + tid;
            int row = slot >> 3;
            int cc = (slot & 7) << 2;
            CPASYNC16(cvta_s(Bf + buf * 2304 + row * 36 + cc),
                      d_Wfc_t + (size_t)(ctan * 64 + row) * (2 * HH) + k0 + kc + cc);
        }
    };

    stage(0, 0); CPCOMMIT();
    stage(1, 32); CPCOMMIT();
    const int nc = 16;
    for (int c = 0; c < nc; ++c) {
        if (c + 2 < nc) stage((c + 2) % 3, (c + 2) * 32);
        CPCOMMIT();
        CPWAIT(2);
        __syncthreads();
        const float* A = Af + (c % 3) * 4608;
        const uint32_t* B = Bf + (c % 3) * 2304;
#pragma unroll
        for (int kk = 0; kk < 4; ++kk) {
            uint32_t a[2][4], b[4][2];
#pragma unroll
            for (int mt = 0; mt < 2; ++mt) {
                int r = wm * 32 + mt * 16 + gp;
                a[mt][0] = f2tf32(A[r * 36 + kk * 8 + tg]);
                a[mt][1] = f2tf32(A[(r + 8) * 36 + kk * 8 + tg]);
                a[mt][2] = f2tf32(A[r * 36 + kk * 8 + tg + 4]);
                a[mt][3] = f2tf32(A[(r + 8) * 36 + kk * 8 + tg + 4]);
            }
#pragma unroll
            for (int nt = 0; nt < 4; ++nt) {
                int n = wn * 32 + nt * 8 + gp;
                b[nt][0] = B[n * 36 + kk * 8 + tg];
                b[nt][1] = B[n * 36 + kk * 8 + tg + 4];
            }
#pragma unroll
            for (int mt = 0; mt < 2; ++mt)
#pragma unroll
                for (int nt = 0; nt < 4; ++nt)
                    mma_tf32(acc[mt][nt], a[mt], b[nt]);
        }
        __syncthreads();
    }
#pragma unroll
    for (int mt = 0; mt < 2; ++mt)
#pragma unroll
        for (int nt = 0; nt < 4; ++nt) {
            int gm0 = ctam * 128 + wm * 32 + mt * 16 + gp;
            int gn = ctan * 64 + wn * 32 + nt * 8 + tg * 2;
            *(float2*)(part + (size_t)gm0 * OO + gn) =
                make_float2(acc[mt][nt][0], acc[mt][nt][1]);
            *(float2*)(part + (size_t)(gm0 + 8) * OO + gn) =
                make_float2(acc[mt][nt][2], acc[mt][nt][3]);
        }
}

// ========== attention (cp.async pipelined single-pass softmax) ================
__device__ __forceinline__ void attn_dev(int b, int tatt, const float* __restrict__ enc,
                                         const float* __restrict__ hcur,
                                         float* __restrict__ out, int par, char* dyn,
                                         float* s_scores, float* s_m, float* s_l)
{
    float* es = (float*)dyn;
    const int tid = threadIdx.x;
    const int lane = tid & 31;
    const int w = tid >> 5;

    const float* hb = hcur + (size_t)b * HH;
    float hreg[32];
#pragma unroll
    for (int i = 0; i < 32; ++i) hreg[i] = hb[i * 32 + lane];

    const float* encb = enc + (size_t)b * SS * HH;
#pragma unroll
    for (int p = 0; p < 3; ++p) {
        const float* gsrc = encb + (size_t)(w * 16 + p) * HH;
        float* sb = es + ((size_t)(p % 3) * 8 + w) * 1024;
#pragma unroll
        for (int q = 0; q < 8; ++q)
            CPASYNC16(cvta_s(sb + q * 128 + lane * 4), gsrc + q * 128 + lane * 4);
        CPCOMMIT();
    }

    float m = -1e30f, l = 0.f;
    float ctx[32];
#pragma unroll
    for (int i = 0; i < 32; ++i) ctx[i] = 0.f;

    for (int j = 0; j < 16; ++j) {
        CPWAIT(2);
        __syncwarp();
        const float* e = es + ((size_t)(j % 3) * 8 + w) * 1024;
        float dot = 0.f;
#pragma unroll
        for (int i = 0; i < 32; ++i) dot += hreg[i] * e[i * 32 + lane];
#pragma unroll
        for (int o = 16; o; o >>= 1) dot += __shfl_xor_sync(0xffffffffu, dot, o);
        if (lane == 0) s_scores[w * 16 + j] = dot;

        float nm = fmaxf(m, dot);
        float al = __expf(m - nm);
        float p = __expf(dot - nm);
        l = l * al + p;
#pragma unroll
        for (int i = 0; i < 32; ++i) ctx[i] = ctx[i] * al + p * e[i * 32 + lane];
        m = nm;
        __syncwarp();
        if (j + 3 < 16) {
            const float* gsrc = encb + (size_t)(w * 16 + j + 3) * HH;
            float* sb = es + ((size_t)(j % 3) * 8 + w) * 1024;
#pragma unroll
            for (int q = 0; q < 8; ++q)
                CPASYNC16(cvta_s(sb + q * 128 + lane * 4), gsrc + q * 128 + lane * 4);
        }
        CPCOMMIT();
    }
    CPWAIT(0);
    if (lane == 0) { s_m[w] = m; s_l[w] = l; }
    __syncthreads();

    float M = -1e30f;
#pragma unroll
    for (int i = 0; i < 8; ++i) M = fmaxf(M, s_m[i]);
    float L = 0.f;
#pragma unroll
    for (int i = 0; i < 8; ++i) L += s_l[i] * __expf(s_m[i] - M);

    float sc = __expf(m - M);
    float* cs = es + (size_t)w * 1024;
#pragma unroll
    for (int i = 0; i < 32; ++i) cs[i * 32 + lane] = ctx[i] * sc;
    __syncthreads();

    float* ubuf = d_u[par];
    for (int kk = tid; kk < HH; kk += 256) {
        float sum = 0.f;
#pragma unroll
        for (int ww = 0; ww < 8; ++ww) sum += es[(size_t)ww * 1024 + kk];
        ubuf[(size_t)b * 2 * HH + kk] = sum / L;
        ubuf[(size_t)b * 2 * HH + HH + kk] = hb[kk];
    }
    if (tid < SS) {
        float p = __expf(s_scores[tid] - M) / L;
        out[(size_t)BB * TT * OO + (size_t)b * TT * SS + (size_t)tatt * SS + tid] = p;
    }
}

// ---------------- kernels -----------------------------------------------------
__global__ void k_init() {
    int g = blockIdx.x * 256 + threadIdx.x;  // 65536 float4s per array
    float4 z = make_float4(0.f, 0.f, 0.f, 0.f);
    ((float4*)d_h[1])[g] = z;
    ((float4*)d_ht32[1])[g] = z;
    ((float4*)d_c)[g] = z;
}

__global__ void __launch_bounds__(256) k_convert(const float* __restrict__ Wih,
                                                 const float* __restrict__ Whh,
                                                 const float* __restrict__ Wfc) {
    int g = blockIdx.x * 256 + threadIdx.x;
    int stride = gridDim.x * 256;
    for (int i = g; i < G4 * II; i += stride) d_Wih_t[i] = f2tf32(Wih[i]);
    for (int i = g; i < G4 * HH; i += stride) {
        int n = i >> 10;
        int k = i & 1023;
        d_Whh_t[(size_t)n * HH + kperm(k)] = f2tf32(Whh[i]);
    }
    for (int i = g; i < OO * 2 * HH; i += stride) d_Wfc_t[i] = f2tf32(Wfc[i]);
}

__global__ void __launch_bounds__(256, 2) k_pre(const float* __restrict__ st,
                                                const float* __restrict__ bih,
                                                const float* __restrict__ bhh) {
    extern __shared__ char dyn[];
    gemm_pre(blockIdx.x >> 5, blockIdx.x & 31, st, d_Wih_t, bih, bhh, d_Xg, II, dyn);
}

__global__ void __launch_bounds__(256, 2) kA(int t, int nG, int nA, int nP,
                                             const float* __restrict__ enc,
                                             const float* __restrict__ bfc,
                                             float* __restrict__ out) {
    extern __shared__ char dyn[];
    __shared__ float s_scores[SS];
    __shared__ float s_m[8], s_l[8];
    int bid = blockIdx.x;
    if (bid < nG) {
        gatescell_dev(bid >> 5, bid & 31,
                      d_ht32[(t + 1) & 1], d_Xg + (size_t)t * BB * G4,
                      d_h[t & 1], d_ht32[t & 1], dyn);
    } else if (bid < nG + nA) {
        // attention for step t-1: each CTA handles 2 batches
        int ta = t - 1;
        int b0 = (bid - nG) * 2;
#pragma unroll
        for (int sub = 0; sub < 2; ++sub) {
            attn_dev(b0 + sub, ta, enc, d_h[ta & 1], out, ta & 1, dyn,
                     s_scores, s_m, s_l);
            __syncthreads();
        }
    } else if (bid < nG + nA + nP) {
        int f = bid - nG - nA;     // 0..31
        int tfc = t - 2;
        int ks = f & 3;
        int ctan = (f >> 2) & 3;
        int ctam = f >> 4;
        fcpart_dev(ctam, ctan, ks, d_u[tfc & 1], d_fcp[tfc & 1][ks]);
    } else {
        int tr = t - 3;
        const float* p0 = d_fcp[tr & 1][0];
        const float* p1 = d_fcp[tr & 1][1];
        const float* p2 = d_fcp[tr & 1][2];
        const float* p3 = d_fcp[tr & 1][3];
        int bidr = bid - nG - nA - nP;  // 0..15
        for (int e = bidr * 256 + threadIdx.x; e < BB * OO; e += 16 * 256) {
            int b = e >> 8;
            int o = e & 255;
            float v = p0[e] + p1[e] + p2[e] + p3[e] + bfc[o];
            out[(size_t)b * TT * OO + (size_t)tr * OO + o] = v;
        }
    }
}

// ---------------- launch --------------------------------------------------------
extern "C" void kernel_launch(void* const* d_in, const int* in_sizes, int n_in,
                              void* d_out, int out_size) {
    const float* st  = (const float*)d_in[0];
    const float* enc = (const float*)d_in[1];
    const float* Wih = (const float*)d_in[2];
    const float* Whh = (const float*)d_in[3];
    const float* bih = (const float*)d_in[4];
    const float* bhh = (const float*)d_in[5];
    const float* Wfc = (const float*)d_in[6];
    const float* bfc = (const float*)d_in[7];
    float* out = (float*)d_out;

    static const int DYN_GEMM = 73728;
    static const int DYN_KA = 110592;   // gates: 36864(A) + 73728(B); attn needs 98304
    cudaFuncSetAttribute(k_pre, cudaFuncAttributeMaxDynamicSharedMemorySize, DYN_GEMM);
    cudaFuncSetAttribute(kA, cudaFuncAttributeMaxDynamicSharedMemorySize, DYN_KA);

    k_init<<<256, 256>>>();                       // 0
    k_convert<<<592, 256>>>(Wih, Whh, Wfc);       // 1
    k_pre<<<2048, 256, DYN_GEMM>>>(st, bih, bhh); // 2

    // 3: kA(0), 4: kA(1), 5: kA(2) <- ncu -s 5 profiles mixed gates+attn+fc
    for (int t = 0; t <= TT + 2; ++t) {
        int nG = (t < TT) ? 128 : 0;                     // gates+cell step t
        int nA = (t >= 1 && t <= TT) ? 128 : 0;          // attention step t-1 (2 batches/CTA)
        int nP = (t >= 2 && t <= TT + 1) ? 32 : 0;       // fc partials step t-2
        int nR = (t >= 3) ? 16 : 0;                      // fc reduce step t-3
        kA<<<nG + nA + nP + nR, 256, DYN_KA>>>(t, nG, nA, nP, enc, bfc, out);
    }
}